// round 6
// baseline (speedup 1.0000x reference)
#include <cuda_runtime.h>
#include <cuda_bf16.h>
#include <math.h>
#include <stdint.h>

#define BB 2
#define SS 1024
#define DD 768
#define DINNER 1536
#define NH 24
#define HD 64
#define DS 64
#define DMLP 1920
#define PROJ 6936
#define NTOK (BB*SS)

// ---------------- fp32 scratch ----------------
__device__ __align__(16) float g_proj [NTOK*PROJ];
__device__ __align__(16) float g_Bm   [NTOK*NH*DS];
__device__ __align__(16) float g_Cm   [NTOK*NH*DS];
__device__ __align__(16) float g_dth  [NTOK*NH*(DS/2)];
__device__ __align__(16) float g_alpha[NTOK*NH];
__device__ __align__(16) float g_sumx [NTOK*NH];
__device__ __align__(16) float g_xs   [NTOK*DINNER];
__device__ __align__(16) float g_y    [NTOK*DINNER];
__device__ __align__(16) float g_x2   [NTOK*DD];
__device__ __align__(16) float g_g    [NTOK*DMLP];
__device__ __align__(16) float g_u    [NTOK*DMLP];

// ---------------- bf16 split buffers (hi/lo) ----------------
__device__ __align__(16) __nv_bfloat16 b_h_hi [NTOK*DD],    b_h_lo [NTOK*DD];
__device__ __align__(16) __nv_bfloat16 b_w1_hi[PROJ*DD],    b_w1_lo[PROJ*DD];
__device__ __align__(16) __nv_bfloat16 b_y_hi [NTOK*DINNER],b_y_lo [NTOK*DINNER];
__device__ __align__(16) __nv_bfloat16 b_w2_hi[DD*DINNER],  b_w2_lo[DD*DINNER];
__device__ __align__(16) __nv_bfloat16 b_h2_hi[NTOK*DD],    b_h2_lo[NTOK*DD];
__device__ __align__(16) __nv_bfloat16 b_wg_hi[DMLP*DD],    b_wg_lo[DMLP*DD];
__device__ __align__(16) __nv_bfloat16 b_wu_hi[DMLP*DD],    b_wu_lo[DMLP*DD];
__device__ __align__(16) __nv_bfloat16 b_gg_hi[NTOK*DMLP],  b_gg_lo[NTOK*DMLP];
__device__ __align__(16) __nv_bfloat16 b_wd_hi[DD*DMLP],    b_wd_lo[DD*DMLP];

__device__ __forceinline__ float* resolve(int id) {
    switch (id) {
        case 2: return g_proj;
        case 3: return g_y;
        case 4: return g_x2;
        case 6: return g_g;
        case 7: return g_u;
    }
    return nullptr;
}
__device__ __forceinline__ __nv_bfloat16* resolve_b(int id) {
    switch (id) {
        case 1: return b_h_hi;  case 2: return b_h_lo;
        case 3: return b_w1_hi; case 4: return b_w1_lo;
        case 5: return b_y_hi;  case 6: return b_y_lo;
        case 7: return b_w2_hi; case 8: return b_w2_lo;
        case 9: return b_h2_hi; case 10: return b_h2_lo;
        case 11: return b_wg_hi;case 12: return b_wg_lo;
        case 13: return b_wu_hi;case 14: return b_wu_lo;
        case 15: return b_gg_hi;case 16: return b_gg_lo;
        case 17: return b_wd_hi;case 18: return b_wd_lo;
    }
    return nullptr;
}

__device__ __forceinline__ uint32_t smem_u32(const void* p) {
    uint32_t a;
    asm("{ .reg .u64 t; cvta.to.shared.u64 t, %1; cvt.u32.u64 %0, t; }"
        : "=r"(a) : "l"(p));
    return a;
}
__device__ __forceinline__ void ldsm_x4(uint32_t* r, uint32_t addr) {
    asm volatile("ldmatrix.sync.aligned.m8n8.x4.shared.b16 {%0,%1,%2,%3}, [%4];"
                 : "=r"(r[0]), "=r"(r[1]), "=r"(r[2]), "=r"(r[3]) : "r"(addr));
}
__device__ __forceinline__ void mma16816(float* d, const uint32_t* a,
                                         const uint32_t b0, const uint32_t b1) {
    asm volatile(
        "mma.sync.aligned.m16n8k16.row.col.f32.bf16.bf16.f32 "
        "{%0,%1,%2,%3}, {%4,%5,%6,%7}, {%8,%9}, {%0,%1,%2,%3};"
        : "+f"(d[0]), "+f"(d[1]), "+f"(d[2]), "+f"(d[3])
        : "r"(a[0]), "r"(a[1]), "r"(a[2]), "r"(a[3]), "r"(b0), "r"(b1));
}
__device__ __forceinline__ void cp16(uint32_t dst, const void* src) {
    asm volatile("cp.async.cg.shared.global [%0], [%1], 16;"
                 :: "r"(dst), "l"(src) : "memory");
}
__device__ __forceinline__ void cp16z(uint32_t dst, const void* src, int srcsz) {
    asm volatile("cp.async.cg.shared.global [%0], [%1], 16, %2;"
                 :: "r"(dst), "l"(src), "r"(srcsz) : "memory");
}
#define CP_COMMIT() asm volatile("cp.async.commit_group;" ::: "memory")
#define CP_WAIT0()  asm volatile("cp.async.wait_group 0;" ::: "memory")

// ---------------- HMMA GEMM, cp.async double-buffered ----------------
// CTA 128(M) x 64(N), BK=32, 256 threads = 8 warps (4x2), warp tile 32x32.
#define PADK 40
#define ATILE (128*PADK)          // elems
#define WTILE (64*PADK)
#define BUFE  (2*ATILE + 2*WTILE) // 15360 elems per stage
#define GSMEM (2*BUFE*2)          // 61440 bytes

__global__ __launch_bounds__(256)
void gemm_mma(int aHi, int aLo, int wHi, int wLo,
              const float* __restrict__ Rext, int Rid,
              float* __restrict__ Cext, int Cid,
              int M, int N, int K, int epi) {
    extern __shared__ __nv_bfloat16 sm[];
    const __nv_bfloat16* Ah = resolve_b(aHi);
    const __nv_bfloat16* Al = resolve_b(aLo);
    const __nv_bfloat16* Wh = resolve_b(wHi);
    const __nv_bfloat16* Wl = resolve_b(wLo);
    float* C = Cext ? Cext : resolve(Cid);
    const float* R = epi ? (Rext ? Rext : resolve(Rid)) : nullptr;

    int tid = threadIdx.x, lane = tid & 31, warp = tid >> 5;
    int wm = (warp >> 1) * 32, wn = (warp & 1) * 32;
    int m0 = blockIdx.y * 128, n0 = blockIdx.x * 64;

    float acc[2][4][4];
#pragma unroll
    for (int t = 0; t < 2; ++t)
#pragma unroll
        for (int j = 0; j < 4; ++j)
#pragma unroll
            for (int q = 0; q < 4; ++q) acc[t][j][q] = 0.f;

    int lr = tid >> 2;           // 0..63
    int lc = (tid & 3) * 8;      // bf16 col offset (16B chunk)
    int wsrc_row = (n0 + lr < N) ? (n0 + lr) : 0;
    int wsz = (n0 + lr < N) ? 16 : 0;

    int a_row = (lane & 15), a_colsel = (lane >> 4) * 8;
    int w_row = (lane & 7) + ((lane >> 4) << 3), w_colsel = ((lane >> 3) & 1) * 8;

    int iters = K >> 5;

    // prologue: stage 0
    {
        __nv_bfloat16* base = sm;
#pragma unroll
        for (int half = 0; half < 2; ++half) {
            int row = lr + half * 64;
            cp16(smem_u32(base + row * PADK + lc), Ah + (size_t)(m0 + row) * K + lc);
            cp16(smem_u32(base + ATILE + row * PADK + lc), Al + (size_t)(m0 + row) * K + lc);
        }
        cp16z(smem_u32(base + 2 * ATILE + lr * PADK + lc),
              Wh + (size_t)wsrc_row * K + lc, wsz);
        cp16z(smem_u32(base + 2 * ATILE + WTILE + lr * PADK + lc),
              Wl + (size_t)wsrc_row * K + lc, wsz);
        CP_COMMIT();
    }

    for (int j = 0; j < iters; ++j) {
        CP_WAIT0();
        __syncthreads();

        if (j + 1 < iters) {
            int k0 = (j + 1) << 5;
            __nv_bfloat16* base = sm + ((j + 1) & 1) * BUFE;
#pragma unroll
            for (int half = 0; half < 2; ++half) {
                int row = lr + half * 64;
                cp16(smem_u32(base + row * PADK + lc),
                     Ah + (size_t)(m0 + row) * K + k0 + lc);
                cp16(smem_u32(base + ATILE + row * PADK + lc),
                     Al + (size_t)(m0 + row) * K + k0 + lc);
            }
            cp16z(smem_u32(base + 2 * ATILE + lr * PADK + lc),
                  Wh + (size_t)wsrc_row * K + k0 + lc, wsz);
            cp16z(smem_u32(base + 2 * ATILE + WTILE + lr * PADK + lc),
                  Wl + (size_t)wsrc_row * K + k0 + lc, wsz);
            CP_COMMIT();
        }

        const __nv_bfloat16* sAh = sm + (j & 1) * BUFE;
        const __nv_bfloat16* sAl = sAh + ATILE;
        const __nv_bfloat16* sWh = sAl + ATILE;
        const __nv_bfloat16* sWl = sWh + WTILE;

        uint32_t ah[2][2][4], al[2][2][4], wh[2][2][4], wl[2][2][4];
#pragma unroll
        for (int t = 0; t < 2; ++t)
#pragma unroll
            for (int s = 0; s < 2; ++s) {
                int row = wm + t * 16 + a_row;
                int col = s * 16 + a_colsel;
                ldsm_x4(ah[t][s], smem_u32(&sAh[row * PADK + col]));
                ldsm_x4(al[t][s], smem_u32(&sAl[row * PADK + col]));
            }
#pragma unroll
        for (int p = 0; p < 2; ++p)
#pragma unroll
            for (int s = 0; s < 2; ++s) {
                int row = wn + p * 16 + w_row;
                int col = s * 16 + w_colsel;
                ldsm_x4(wh[p][s], smem_u32(&sWh[row * PADK + col]));
                ldsm_x4(wl[p][s], smem_u32(&sWl[row * PADK + col]));
            }

#pragma unroll
        for (int t = 0; t < 2; ++t)
#pragma unroll
            for (int j2 = 0; j2 < 4; ++j2) {
                int p = j2 >> 1, i2 = (j2 & 1) * 2;
#pragma unroll
                for (int s = 0; s < 2; ++s) {
                    mma16816(acc[t][j2], ah[t][s], wh[p][s][i2], wh[p][s][i2 + 1]);
                    mma16816(acc[t][j2], ah[t][s], wl[p][s][i2], wl[p][s][i2 + 1]);
                    mma16816(acc[t][j2], al[t][s], wh[p][s][i2], wh[p][s][i2 + 1]);
                }
            }
        // no trailing sync: next iteration's WAIT0+syncthreads protects buffers
    }

    // epilogue
#pragma unroll
    for (int t = 0; t < 2; ++t) {
        int r0 = m0 + wm + t * 16 + (lane >> 2);
#pragma unroll
        for (int j = 0; j < 4; ++j) {
            int col = n0 + wn + j * 8 + (lane & 3) * 2;
            if (col < N) {
                float2 v0 = make_float2(acc[t][j][0], acc[t][j][1]);
                float2 v1 = make_float2(acc[t][j][2], acc[t][j][3]);
                if (epi) {
                    float2 r;
                    r = *(const float2*)(R + (size_t)r0 * N + col);
                    v0.x += r.x; v0.y += r.y;
                    r = *(const float2*)(R + (size_t)(r0 + 8) * N + col);
                    v1.x += r.x; v1.y += r.y;
                }
                *(float2*)(C + (size_t)r0 * N + col) = v0;
                *(float2*)(C + (size_t)(r0 + 8) * N + col) = v1;
            }
        }
    }
}

// ---------------- fused weight split ----------------
__global__ void cvt_all(const float* __restrict__ w1, const float* __restrict__ w2,
                        const float* __restrict__ wg, const float* __restrict__ wu,
                        const float* __restrict__ wd) {
    int i0 = blockIdx.x * blockDim.x + threadIdx.x;
    int stride = gridDim.x * blockDim.x;
#define SPLIT(src, hi, lo, n)                                            \
    for (int i = i0; i < (n); i += stride) {                             \
        float v = src[i];                                                \
        __nv_bfloat16 hh = __float2bfloat16(v);                          \
        hi[i] = hh;                                                      \
        lo[i] = __float2bfloat16(v - __bfloat162float(hh));              \
    }
    SPLIT(w1, b_w1_hi, b_w1_lo, PROJ * DD)
    SPLIT(w2, b_w2_hi, b_w2_lo, DD * DINNER)
    SPLIT(wg, b_wg_hi, b_wg_lo, DMLP * DD)
    SPLIT(wu, b_wu_hi, b_wu_lo, DMLP * DD)
    SPLIT(wd, b_wd_hi, b_wd_lo, DD * DMLP)
#undef SPLIT
}

// ---------------- rmsnorm(768) -> bf16 hi/lo ----------------
__global__ void rmsnorm_b16(const float* __restrict__ src_ext, int src_id,
                            const float* __restrict__ w, int hiId, int loId) {
    const float* src = src_ext ? src_ext : resolve(src_id);
    __nv_bfloat16* hi = resolve_b(hiId);
    __nv_bfloat16* lo = resolve_b(loId);
    int t = blockIdx.x;
    const float* row = src + (size_t)t * DD;
    float s = 0.f;
    for (int i = threadIdx.x; i < DD; i += blockDim.x) { float v = row[i]; s += v * v; }
    __shared__ float sh[8];
    for (int o = 16; o; o >>= 1) s += __shfl_down_sync(0xffffffffu, s, o);
    if ((threadIdx.x & 31) == 0) sh[threadIdx.x >> 5] = s;
    __syncthreads();
    if (threadIdx.x < 8) {
        float v = sh[threadIdx.x];
        for (int o = 4; o; o >>= 1) v += __shfl_down_sync(0xffu, v, o);
        if (threadIdx.x == 0) sh[0] = v;
    }
    __syncthreads();
    float scale = rsqrtf(sh[0] / (float)DD + 1e-5f);
    for (int i = threadIdx.x; i < DD; i += blockDim.x) {
        float v = row[i] * scale * w[i];
        __nv_bfloat16 h = __float2bfloat16(v);
        hi[(size_t)t * DD + i] = h;
        lo[(size_t)t * DD + i] = __float2bfloat16(v - __bfloat162float(h));
    }
}

// ---------------- per-(token,head) prep ----------------
__global__ void prep_kernel(const float* __restrict__ A_log,
                            const float* __restrict__ dt_bias,
                            const float* __restrict__ B_bias,
                            const float* __restrict__ C_bias,
                            const float* __restrict__ Bnw,
                            const float* __restrict__ Cnw) {
    const unsigned full = 0xffffffffu;
    int lane = threadIdx.x & 31;
    int unit = blockIdx.x * (blockDim.x >> 5) + (threadIdx.x >> 5);
    if (unit >= NTOK * NH) return;
    int t = unit / NH, h = unit % NH;
    const float* p = g_proj + (size_t)t * PROJ;
    {
        const float* br = p + 2 * DINNER + h * DS;
        float b0 = br[lane], b1 = br[lane + 32];
        float ss = b0 * b0 + b1 * b1;
        for (int o = 16; o; o >>= 1) ss += __shfl_xor_sync(full, ss, o);
        float sc = rsqrtf(ss / 64.f + 1e-5f);
        float* out = g_Bm + (size_t)unit * DS;
        out[lane]      = b0 * sc * Bnw[lane]      + B_bias[h * DS + lane];
        out[lane + 32] = b1 * sc * Bnw[lane + 32] + B_bias[h * DS + lane + 32];
    }
    {
        const float* cr = p + 2 * DINNER + NH * DS + h * DS;
        float c0 = cr[lane], c1 = cr[lane + 32];
        float ss = c0 * c0 + c1 * c1;
        for (int o = 16; o; o >>= 1) ss += __shfl_xor_sync(full, ss, o);
        float sc = rsqrtf(ss / 64.f + 1e-5f);
        float* out = g_Cm + (size_t)unit * DS;
        out[lane]      = c0 * sc * Cnw[lane]      + C_bias[h * DS + lane];
        out[lane + 32] = c1 * sc * Cnw[lane + 32] + C_bias[h * DS + lane + 32];
    }
    {
        float raw = p[2 * DINNER + 2 * NH * DS + h] + dt_bias[h];
        float dtv = (raw > 20.f) ? raw : log1pf(expf(raw));
        float A = -expf(A_log[h]) * dtv;
        float al = expf(A);
        float gam = (al - 1.f) / (A + 1e-6f) * 0.5f + 1.f;
        if (lane == 0) g_alpha[unit] = al;
        g_dth[(size_t)unit * 32 + lane] =
            dtv * p[2 * DINNER + 2 * NH * DS + NH + h * 32 + lane];
        const float* xr = p + DINNER + h * HD;
        float x0 = xr[lane], x1 = xr[lane + 32];
        float* xo = g_xs + (size_t)unit * HD;
        xo[lane]      = x0 * gam;
        xo[lane + 32] = x1 * gam;
        float s = x0 + x1;
        for (int o = 16; o; o >>= 1) s += __shfl_xor_sync(full, s, o);
        if (lane == 0) g_sumx[unit] = s;
    }
}

// ---------------- rope: parallel block-scan over s per (b,h), loop r ----------------
__global__ __launch_bounds__(1024)
void rope_kernel() {
    const unsigned full = 0xffffffffu;
    int bh = blockIdx.x;
    int b = bh / NH, h = bh % NH;
    int s = threadIdx.x;
    int lane = s & 31, warp = s >> 5;
    size_t unit = (size_t)(b * SS + s) * NH + h;
    float2* Bp = (float2*)(g_Bm + unit * DS);
    float2* Cp = (float2*)(g_Cm + unit * DS);
    const float* dthp = g_dth + unit * 32;
    __shared__ float wsum[32];

#pragma unroll 1
    for (int r = 0; r < 32; ++r) {
        float v = dthp[r];
#pragma unroll
        for (int o = 1; o < 32; o <<= 1) {
            float n = __shfl_up_sync(full, v, o);
            if (lane >= o) v += n;
        }
        if (lane == 31) wsum[warp] = v;
        __syncthreads();
        if (warp == 0) {
            float w = wsum[lane];
#pragma unroll
            for (int o = 1; o < 32; o <<= 1) {
                float n = __shfl_up_sync(full, w, o);
                if (lane >= o) w += n;
            }
            wsum[lane] = w;
        }
        __syncthreads();
        float ang = v + (warp > 0 ? wsum[warp - 1] : 0.f);
        float sn, c;
        sincosf(ang, &sn, &c);
        float2 bv = Bp[r];
        Bp[r] = make_float2(c * bv.x - sn * bv.y, sn * bv.x + c * bv.y);
        float2 cv = Cp[r];
        Cp[r] = make_float2(c * cv.x - sn * cv.y, sn * cv.x + c * cv.y);
        __syncthreads();
    }
}

// ---------------- SSM scan: warp-independent, no barriers, reg prefetch ----------------
__global__ __launch_bounds__(1024)
void scan_kernel() {
    int bh = blockIdx.x;
    int b = bh / NH, h = bh % NH;
    int warp = threadIdx.x >> 5, lane = threadIdx.x & 31;
    int p0 = warp * 2, p1 = p0 + 1;

    const float* B  = g_Bm + ((size_t)(b * SS) * NH + h) * DS;
    const float* Cc = g_Cm + ((size_t)(b * SS) * NH + h) * DS;
    const float* xs = g_xs + ((size_t)(b * SS) * NH + h) * HD;
    const float* alp = g_alpha + (size_t)(b * SS) * NH + h;
    float* yo = g_y + (size_t)(b * SS) * DINNER + h * HD;
    const int strideU = NH * DS;

    float h00 = 0.f, h01 = 0.f, h10 = 0.f, h11 = 0.f;
    float nB0 = B[lane], nB1 = B[lane + 32];
    float nC0 = Cc[lane], nC1 = Cc[lane + 32];
    float nx0 = xs[p0], nx1 = xs[p1];
    float nal = *alp;

    for (int s = 0; s < SS; ++s) {
        float B0 = nB0, B1 = nB1, C0 = nC0, C1 = nC1;
        float x0 = nx0, x1 = nx1, al = nal;
        if (s + 1 < SS) {
            B += strideU; Cc += strideU; xs += strideU; alp += NH;
            nB0 = __ldg(B + lane);  nB1 = __ldg(B + lane + 32);
            nC0 = __ldg(Cc + lane); nC1 = __ldg(Cc + lane + 32);
            nx0 = __ldg(xs + p0);   nx1 = __ldg(xs + p1);
            nal = __ldg(alp);
        }
        h00 = h00 * al + B0 * x0;
        h01 = h01 * al + B1 * x0;
        h10 = h10 * al + B0 * x1;
        h11 = h11 * al + B1 * x1;
        float y0 = h00 * C0 + h01 * C1;
        float y1 = h10 * C0 + h11 * C1;
#pragma unroll
        for (int o = 16; o; o >>= 1) {
            y0 += __shfl_down_sync(0xffffffffu, y0, o);
            y1 += __shfl_down_sync(0xffffffffu, y1, o);
        }
        if (lane == 0) { yo[p0] = y0; yo[p1] = y1; }
        yo += DINNER;
    }
}

// ---------------- gate ----------------
__global__ void gate_b16(const float* __restrict__ Dp) {
    int idx = blockIdx.x * blockDim.x + threadIdx.x;
    if (idx >= NTOK * DINNER) return;
    int t = idx / DINNER, c = idx % DINNER;
    int h = c / HD;
    float z = g_proj[(size_t)t * PROJ + c];
    float y = g_y[idx] + Dp[h] * g_sumx[t * NH + h];
    float v = y * (z / (1.f + expf(-z)));
    __nv_bfloat16 hv = __float2bfloat16(v);
    b_y_hi[idx] = hv;
    b_y_lo[idx] = __float2bfloat16(v - __bfloat162float(hv));
}

// ---------------- mlp activation ----------------
__global__ void silumul_b16() {
    int i = blockIdx.x * blockDim.x + threadIdx.x;
    if (i >= NTOK * DMLP) return;
    float g = g_g[i];
    float v = g / (1.f + expf(-g)) * g_u[i];
    __nv_bfloat16 hv = __float2bfloat16(v);
    b_gg_hi[i] = hv;
    b_gg_lo[i] = __float2bfloat16(v - __bfloat162float(hv));
}

// ---------------- launch ----------------
extern "C" void kernel_launch(void* const* d_in, const int* in_sizes, int n_in,
                              void* d_out, int out_size) {
    const float* x         = (const float*)d_in[0];
    const float* norm1_w   = (const float*)d_in[1];
    const float* norm2_w   = (const float*)d_in[2];
    const float* in_proj_w = (const float*)d_in[3];
    const float* out_proj_w= (const float*)d_in[4];
    const float* A_log     = (const float*)d_in[5];
    const float* Dp        = (const float*)d_in[6];
    const float* dt_bias   = (const float*)d_in[7];
    const float* B_bias    = (const float*)d_in[8];
    const float* C_bias    = (const float*)d_in[9];
    const float* Bnorm_w   = (const float*)d_in[10];
    const float* Cnorm_w   = (const float*)d_in[11];
    const float* mlp_gate_w= (const float*)d_in[12];
    const float* mlp_up_w  = (const float*)d_in[13];
    const float* mlp_down_w= (const float*)d_in[14];
    float* out = (float*)d_out;

    static int smem_set = 0;
    if (!smem_set) {
        cudaFuncSetAttribute(gemm_mma, cudaFuncAttributeMaxDynamicSharedMemorySize, GSMEM);
        smem_set = 1;
    }

    cvt_all<<<(PROJ * DD + 255) / 256, 256>>>(in_proj_w, out_proj_w,
                                              mlp_gate_w, mlp_up_w, mlp_down_w);

    rmsnorm_b16<<<NTOK, 256>>>(x, 0, norm1_w, 1, 2);

    gemm_mma<<<dim3((PROJ + 63) / 64, NTOK / 128), 256, GSMEM>>>(
        1, 2, 3, 4, nullptr, 0, nullptr, 2, NTOK, PROJ, DD, 0);

    prep_kernel<<<(NTOK * NH + 3) / 4, 128>>>(A_log, dt_bias, B_bias, C_bias,
                                              Bnorm_w, Cnorm_w);
    rope_kernel<<<BB * NH, 1024>>>();
    scan_kernel<<<BB * NH, 1024>>>();
    gate_b16<<<(NTOK * DINNER + 255) / 256, 256>>>(Dp);

    gemm_mma<<<dim3(DD / 64, NTOK / 128), 256, GSMEM>>>(
        5, 6, 7, 8, x, 0, nullptr, 4, NTOK, DD, DINNER, 1);

    rmsnorm_b16<<<NTOK, 256>>>(nullptr, 4, norm2_w, 9, 10);

    gemm_mma<<<dim3(DMLP / 64, NTOK / 128), 256, GSMEM>>>(
        9, 10, 11, 12, nullptr, 0, nullptr, 6, NTOK, DMLP, DD, 0);
    gemm_mma<<<dim3(DMLP / 64, NTOK / 128), 256, GSMEM>>>(
        9, 10, 13, 14, nullptr, 0, nullptr, 7, NTOK, DMLP, DD, 0);

    silumul_b16<<<(NTOK * DMLP + 255) / 256, 256>>>();

    gemm_mma<<<dim3(DD / 64, NTOK / 128), 256, GSMEM>>>(
        15, 16, 17, 18, nullptr, 4, out, 0, NTOK, DD, DMLP, 1);
}